// round 10
// baseline (speedup 1.0000x reference)
#include <cuda_runtime.h>
#include <cstdint>

// Problem shapes (fixed by dataset)
#define BATCH 128
#define CHAN  2048
#define PP    14          // spatial extent
#define HW    196         // 14*14
#define NBOX  36
#define CC    32          // channels per block
#define NTHREADS 512
#define CH_BYTES (HW * 4)         // 784 B per channel row (16B multiple)
#define TSTRIDE  208              // floats per channel in smem (16B multiple)
#define RW    15                  // row-prefix width (P+1)
#define RSTR  211                 // rpf channel stride: 211 % 32 = 19, gcd 1 -> conflict-free
#define TILE_FLOATS (TSTRIDE * CC + 32)   // 6688 (stagger headroom)
#define RPF_FLOATS  (RSTR * CC)           // 6752
#define SMEM_BYTES  ((TILE_FLOATS + RPF_FLOATS) * sizeof(float))  // 53,760 B -> 4 CTAs/SM

// Channel base in floats: linear rows + 16B stagger so the att gather
// bank index = 16j + 4*c4 + hw covers all 32 banks (conflict-free).
__device__ __forceinline__ int chan_base(int c) {
    return TSTRIDE * c + 4 * ((c >> 2) & 7);
}

__device__ __forceinline__ uint32_t smem_u32(const void* p) {
    return (uint32_t)__cvta_generic_to_shared(p);
}

__global__ __launch_bounds__(NTHREADS, 4)
void fused_pool_transpose_region(
    const float* __restrict__ images,   // [B, C, 14, 14]
    const float* __restrict__ boxes,    // [B, 36, 4]
    float* __restrict__ fc,             // [B, C]
    float* __restrict__ att,            // [B, 196, C]
    float* __restrict__ bu)             // [B, 36, C]
{
    extern __shared__ float smem[];
    float* tile = smem;                 // per-channel linear rows, staggered
    float* rpf  = smem + TILE_FLOATS;   // [CC][RSTR]: rpf[c][y*15+x] row prefix

    __shared__ int   bx1[NBOX], by1[NBOX], bx2[NBOX], by2[NBOX];
    __shared__ float barea[NBOX];
    __shared__ alignas(8) unsigned long long mbar;

    const int b   = blockIdx.y;
    const int c0  = blockIdx.x * CC;
    const int tid = threadIdx.x;

    const float* img = images + ((size_t)b * CHAN + c0) * HW;
    const uint32_t mbar_a = smem_u32(&mbar);

    if (tid == 0) {
        asm volatile("mbarrier.init.shared.b64 [%0], %1;" :: "r"(mbar_a), "r"(1) : "memory");
    }

    // ---- box coordinates (replicates reference rounding/degenerate fix) ----
    if (tid < NBOX) {
        const float* bp = boxes + ((size_t)b * NBOX + tid) * 4;
        int x1 = (int)rintf(bp[0] * (float)PP);   // round-half-even == jnp.round
        int y1 = (int)rintf(bp[1] * (float)PP);
        int x2 = (int)rintf(bp[2] * (float)PP);
        int y2 = (int)rintf(bp[3] * (float)PP);
        bool eqx = (x1 == x2);
        if (eqx && x2 <  PP) x2 += 1;
        if (eqx && x2 >= PP && x1 > 0 && x1 == x2) x1 -= 1;
        bool eqy = (y1 == y2);
        if (eqy && y2 <  PP) y2 += 1;
        if (eqy && y2 >= PP && y1 > 0 && y1 == y2) y1 -= 1;
        bx1[tid] = x1; by1[tid] = y1; bx2[tid] = x2; by2[tid] = y2;
        barea[tid] = (float)((y2 - y1) * (x2 - x1));
    }
    __syncthreads();   // mbarrier init + boxes visible

    // ---- tile load via TMA bulk copies: 32 lanes each move one 784B channel
    //      row gmem->smem, bypassing the L1TEX/LSU path entirely ----
    if (tid == 0) {
        asm volatile("mbarrier.arrive.expect_tx.shared.b64 _, [%0], %1;"
                     :: "r"(mbar_a), "r"((uint32_t)(CC * CH_BYTES)) : "memory");
    }
    if (tid < CC) {
        uint32_t dst = smem_u32(tile + chan_base(tid));
        const float* src = img + (size_t)tid * HW;
        asm volatile(
            "cp.async.bulk.shared::cluster.global.mbarrier::complete_tx::bytes "
            "[%0], [%1], %2, [%3];"
            :: "r"(dst), "l"(src), "r"((uint32_t)CH_BYTES), "r"(mbar_a) : "memory");
    }
    // all threads wait for the bulk copies (parity 0)
    {
        uint32_t done;
        asm volatile(
            "{\n\t.reg .pred p;\n\t"
            "mbarrier.try_wait.parity.acquire.cta.shared::cta.b64 p, [%1], %2;\n\t"
            "selp.b32 %0, 1, 0, p;\n\t}"
            : "=r"(done) : "r"(mbar_a), "r"(0) : "memory");
        if (!done) {
            asm volatile(
                "{\n\t.reg .pred P1;\n\t"
                "W_%=:\n\t"
                "mbarrier.try_wait.parity.acquire.cta.shared::cta.b64 P1, [%0], %1, 0x989680;\n\t"
                "@P1 bra.uni D_%=;\n\t"
                "bra.uni W_%=;\n\t"
                "D_%=:\n\t}"
                :: "r"(mbar_a), "r"(0) : "memory");
        }
    }

    // ---- att: transpose; 4 conflict-free LDS -> 1 STG.128.
    //      bank(j) = 16j + 4*c4 + hw covers all 32 banks per warp. ----
    {
        const int c4  = tid & 7;
        const int hw0 = tid >> 3;                  // 0..63
        const float* t0 = tile + chan_base(4 * c4 + 0);
        const float* t1 = tile + chan_base(4 * c4 + 1);
        const float* t2 = tile + chan_base(4 * c4 + 2);
        const float* t3 = tile + chan_base(4 * c4 + 3);
        float* a = att + (size_t)b * HW * CHAN + c0 + (size_t)hw0 * CHAN + 4 * c4;
        #pragma unroll
        for (int hw = hw0; hw < HW; hw += 64, a += 64 * CHAN) {
            float4 v;
            v.x = t0[hw]; v.y = t1[hw]; v.z = t2[hw]; v.w = t3[hw];
            *(float4*)a = v;
        }
    }

    // ---- row prefix: thread per (c, y), natural row order, no swizzle ----
    if (tid < CC * PP) {
        int c = tid / PP, y = tid - c * PP;
        const float* tc  = tile + chan_base(c) + y * PP;
        float*       dst = rpf  + c * RSTR + y * RW;
        dst[0] = 0.0f;
        float acc = 0.0f;
        #pragma unroll
        for (int x = 0; x < PP; x++) { acc += tc[x]; dst[x + 1] = acc; }
    }
    __syncthreads();

    // ---- fc: column-sum of full row sums / 196 (one warp, lanes = c) ----
    if (tid < CC) {
        const float* Rc = rpf + tid * RSTR;
        float s = 0.0f;
        #pragma unroll
        for (int y = 0; y < PP; y++) s += Rc[y * RW + PP];
        fc[(size_t)b * CHAN + c0 + tid] = s * (1.0f / (float)HW);
    }

    // ---- bu: vertical accumulation of row-prefix diffs; warp = box, lane = c
    //      (stride 211 == 19 mod 32 -> conflict-free), uniform y trip count ----
    {
        float* bub = bu + (size_t)b * NBOX * CHAN + c0;
        for (int i = tid; i < NBOX * CC; i += NTHREADS) {
            int r = i >> 5, c = i & 31;
            const float* Rc = rpf + c * RSTR;
            int x1 = bx1[r], y1 = by1[r], x2 = bx2[r], y2 = by2[r];
            float s = 0.0f;
            for (int y = y1; y < y2; y++)
                s += Rc[y * RW + x2] - Rc[y * RW + x1];
            bub[(size_t)r * CHAN + c] = s / barea[r];
        }
    }
}

extern "C" void kernel_launch(void* const* d_in, const int* in_sizes, int n_in,
                              void* d_out, int out_size)
{
    const float* images = (const float*)d_in[0];
    const float* boxes  = (const float*)d_in[1];

    float* out = (float*)d_out;
    float* fc  = out;                                   // [128, 2048]
    float* att = fc  + (size_t)BATCH * CHAN;            // [128, 196, 2048]
    float* bu  = att + (size_t)BATCH * HW * CHAN;       // [128, 36, 2048]

    cudaFuncSetAttribute(fused_pool_transpose_region,
                         cudaFuncAttributeMaxDynamicSharedMemorySize,
                         (int)SMEM_BYTES);

    dim3 grid(CHAN / CC, BATCH);
    fused_pool_transpose_region<<<grid, NTHREADS, SMEM_BYTES>>>(
        images, boxes, fc, att, bu);
}